// round 11
// baseline (speedup 1.0000x reference)
#include <cuda_runtime.h>

// Group ZCA whitening: x (64, 256, 56, 56) fp32, 64 groups of 4 channels.
// R11: per-group pipelined fusion. Grid (NB, NG) with b FASTEST, so group g's
// 64 blocks (bids g*64..g*64+63) are co-scheduled in one wave. Each block:
//   stats(tile) -> per-group monotonic counter -> 64th arrival solves g (fp32)
//   -> bump done[g] -> groupmates spin (near-zero wait, co-resident)
//   -> re-read OWN tile (L2 hit: wave working set 44MB << 126MB L2) -> apply.
// DRAM traffic drops from ~575MB to ~410MB (apply read becomes L2 hits).
// Counters monotonic (round=old/64, wait done[g]>=round+1): graph-replay safe.

#define NB   64      // batches
#define NG   64      // groups
#define NCH  256     // channels
#define SP   3136    // 56*56
#define SP4  784     // SP / 4
#define EPSF 1e-3f

__device__ float g_part[NG * NB * 14];   // [group][batch][4 sums + 10 moments]
__device__ float g_W[NG * 16];
__device__ float g_bias[NG * 4];
__device__ unsigned int g_cnt[NG];       // monotonic arrival counters
__device__ unsigned int g_done[NG];      // monotonic solve-done counters

// ---------------------------------------------------------------------------
// fp32 4x4 symmetric Jacobi solve for group g (validated: rel_err ~3.6e-7).
// All 256 threads of the last-arriving block participate.
// ---------------------------------------------------------------------------
__device__ void solve_group(int g) {
    const int t = threadIdx.x;

    float vals[14];
    if (t < NB) {
        #pragma unroll
        for (int k = 0; k < 14; k++)
            vals[k] = g_part[((size_t)g * NB + t) * 14 + k];
    } else {
        #pragma unroll
        for (int k = 0; k < 14; k++) vals[k] = 0.f;
    }

    const int lane = t & 31;
    const int warp = t >> 5;
    #pragma unroll
    for (int k = 0; k < 14; k++) {
        #pragma unroll
        for (int o = 16; o > 0; o >>= 1)
            vals[k] += __shfl_down_sync(0xffffffffu, vals[k], o);
    }
    __shared__ float sv[2][14];
    if (lane == 0 && warp < 2) {
        #pragma unroll
        for (int k = 0; k < 14; k++) sv[warp][k] = vals[k];
    }
    __syncthreads();

    if (t == 0) {
        float S[4], Q[10];
        #pragma unroll
        for (int k = 0; k < 4; k++) S[k] = sv[0][k] + sv[1][k];
        #pragma unroll
        for (int k = 0; k < 10; k++) Q[k] = sv[0][4 + k] + sv[1][4 + k];

        const float n = (float)NB * (float)SP;
        float m[4];
        #pragma unroll
        for (int k = 0; k < 4; k++) m[k] = S[k] / n;

        float A[4][4];
        const int qi[4][4] = {{0,1,2,3},{1,4,5,6},{2,5,7,8},{3,6,8,9}};
        for (int i = 0; i < 4; i++)
            for (int j = 0; j < 4; j++) {
                float c = Q[qi[i][j]] - n * m[i] * m[j];
                A[i][j] = (1.0f - EPSF) * c + (i == j ? EPSF : 0.0f);
            }

        float V[4][4] = {{1,0,0,0},{0,1,0,0},{0,0,1,0},{0,0,0,1}};
        for (int sweep = 0; sweep < 12; sweep++) {
            float off = fabsf(A[0][1]) + fabsf(A[0][2]) + fabsf(A[0][3])
                      + fabsf(A[1][2]) + fabsf(A[1][3]) + fabsf(A[2][3]);
            if (off < 1e-7f * (fabsf(A[0][0]) + fabsf(A[1][1]) + fabsf(A[2][2]) + fabsf(A[3][3]) + 1e-30f))
                break;
            for (int p = 0; p < 3; p++)
                for (int q = p + 1; q < 4; q++) {
                    float apq = A[p][q];
                    if (fabsf(apq) < 1e-30f) continue;
                    float theta = (A[q][q] - A[p][p]) / (2.0f * apq);
                    float tt = (theta >= 0.0f ? 1.0f : -1.0f) / (fabsf(theta) + sqrtf(theta * theta + 1.0f));
                    float c = 1.0f / sqrtf(tt * tt + 1.0f);
                    float s = tt * c;
                    for (int k = 0; k < 4; k++) {
                        float akp = A[k][p], akq = A[k][q];
                        A[k][p] = c * akp - s * akq;
                        A[k][q] = s * akp + c * akq;
                    }
                    for (int k = 0; k < 4; k++) {
                        float apk = A[p][k], aqk = A[q][k];
                        A[p][k] = c * apk - s * aqk;
                        A[q][k] = s * apk + c * aqk;
                    }
                    for (int k = 0; k < 4; k++) {
                        float vkp = V[k][p], vkq = V[k][q];
                        V[k][p] = c * vkp - s * vkq;
                        V[k][q] = s * vkp + c * vkq;
                    }
                }
        }

        float inv[4];
        #pragma unroll
        for (int k = 0; k < 4; k++) inv[k] = 1.0f / sqrtf(A[k][k] + EPSF);

        for (int i = 0; i < 4; i++) {
            float bsum = 0.0f;
            #pragma unroll
            for (int j = 0; j < 4; j++) {
                float w = 0.0f;
                #pragma unroll
                for (int k = 0; k < 4; k++) w += V[i][k] * inv[k] * V[j][k];
                g_W[g * 16 + i * 4 + j] = w;
                bsum += w * m[j];
            }
            g_bias[g * 4 + i] = bsum;
        }
    }
    __syncthreads();
}

// ---------------------------------------------------------------------------
// Fused per-tile kernel. grid (NB, NG): b = blockIdx.x (FAST), g = blockIdx.y.
// ---------------------------------------------------------------------------
__global__ __launch_bounds__(256, 6) void whiten_pipelined(const float* __restrict__ x,
                                                           float* __restrict__ out) {
    const int b = blockIdx.x;
    const int g = blockIdx.y;
    const int tid = threadIdx.x;

    const size_t base = ((size_t)b * NCH + (size_t)g * 4) * SP;
    const float4* __restrict__ c0 = (const float4*)(x + base);
    const float4* __restrict__ c1 = c0 + SP4;
    const float4* __restrict__ c2 = c0 + 2 * SP4;
    const float4* __restrict__ c3 = c0 + 3 * SP4;

    // ---- Phase A: stats on this tile ----
    {
        float s0 = 0.f, s1 = 0.f, s2 = 0.f, s3 = 0.f;
        float q00 = 0.f, q01 = 0.f, q02 = 0.f, q03 = 0.f;
        float q11 = 0.f, q12 = 0.f, q13 = 0.f;
        float q22 = 0.f, q23 = 0.f, q33 = 0.f;

        for (int i = tid; i < SP4; i += 256) {
            float4 a = c0[i];
            float4 e = c1[i];
            float4 f = c2[i];
            float4 h = c3[i];
            s0 += a.x + a.y + a.z + a.w;
            s1 += e.x + e.y + e.z + e.w;
            s2 += f.x + f.y + f.z + f.w;
            s3 += h.x + h.y + h.z + h.w;
            q00 += a.x*a.x + a.y*a.y + a.z*a.z + a.w*a.w;
            q01 += a.x*e.x + a.y*e.y + a.z*e.z + a.w*e.w;
            q02 += a.x*f.x + a.y*f.y + a.z*f.z + a.w*f.w;
            q03 += a.x*h.x + a.y*h.y + a.z*h.z + a.w*h.w;
            q11 += e.x*e.x + e.y*e.y + e.z*e.z + e.w*e.w;
            q12 += e.x*f.x + e.y*f.y + e.z*f.z + e.w*f.w;
            q13 += e.x*h.x + e.y*h.y + e.z*h.z + e.w*h.w;
            q22 += f.x*f.x + f.y*f.y + f.z*f.z + f.w*f.w;
            q23 += f.x*h.x + f.y*h.y + f.z*h.z + f.w*h.w;
            q33 += h.x*h.x + h.y*h.y + h.z*h.z + h.w*h.w;
        }

        float v[14] = {s0, s1, s2, s3, q00, q01, q02, q03, q11, q12, q13, q22, q23, q33};

        const int lane = tid & 31;
        const int warp = tid >> 5;
        #pragma unroll
        for (int k = 0; k < 14; k++) {
            #pragma unroll
            for (int o = 16; o > 0; o >>= 1)
                v[k] += __shfl_down_sync(0xffffffffu, v[k], o);
        }

        __shared__ float sm[8][14];
        if (lane == 0) {
            #pragma unroll
            for (int k = 0; k < 14; k++) sm[warp][k] = v[k];
        }
        __syncthreads();
        if (tid < 14) {
            float t = 0.f;
            #pragma unroll
            for (int w = 0; w < 8; w++) t += sm[w][tid];
            g_part[((size_t)g * NB + b) * 14 + tid] = t;
        }
        __syncthreads();   // sm reuse safety
    }

    // ---- Phase B: per-group sync + last-arrival solve ----
    __shared__ unsigned int sh_round;
    __shared__ unsigned int sh_last;
    if (tid == 0) {
        __threadfence();                               // publish g_part
        unsigned int old = atomicAdd(&g_cnt[g], 1u);
        sh_round = old >> 6;                           // /NB
        sh_last = ((old & (NB - 1u)) == NB - 1u) ? 1u : 0u;
    }
    __syncthreads();

    if (sh_last) {
        solve_group(g);
        if (tid == 0) {
            __threadfence();                           // publish W, bias
            atomicAdd(&g_done[g], 1u);
        }
    } else if (tid == 0) {
        const unsigned int target = sh_round + 1u;
        while (atomicAdd(&g_done[g], 0u) < target) {
            __nanosleep(32);
        }
    }
    __syncthreads();
    __threadfence();   // order g_W/g_bias reads after flag observation

    // ---- Phase C: apply to OWN tile (L2-resident from Phase A) ----
    __shared__ float Ws[20];
    if (tid < 16) Ws[tid] = g_W[g * 16 + tid];
    if (tid < 4)  Ws[16 + tid] = g_bias[g * 4 + tid];
    __syncthreads();

    const float w00 = Ws[0],  w01 = Ws[1],  w02 = Ws[2],  w03 = Ws[3];
    const float w10 = Ws[4],  w11 = Ws[5],  w12 = Ws[6],  w13 = Ws[7];
    const float w20 = Ws[8],  w21 = Ws[9],  w22 = Ws[10], w23 = Ws[11];
    const float w30 = Ws[12], w31 = Ws[13], w32 = Ws[14], w33 = Ws[15];
    const float b0 = Ws[16], b1 = Ws[17], b2 = Ws[18], b3 = Ws[19];

    float4* __restrict__ o0 = (float4*)(out + base);
    float4* __restrict__ o1 = o0 + SP4;
    float4* __restrict__ o2 = o0 + 2 * SP4;
    float4* __restrict__ o3 = o0 + 3 * SP4;

    for (int i = tid; i < SP4; i += 256) {
        float4 a = __ldcs(c0 + i);
        float4 e = __ldcs(c1 + i);
        float4 f = __ldcs(c2 + i);
        float4 h = __ldcs(c3 + i);

        float4 r0, r1, r2, r3;
        r0.x = fmaf(w00, a.x, fmaf(w01, e.x, fmaf(w02, f.x, fmaf(w03, h.x, -b0))));
        r0.y = fmaf(w00, a.y, fmaf(w01, e.y, fmaf(w02, f.y, fmaf(w03, h.y, -b0))));
        r0.z = fmaf(w00, a.z, fmaf(w01, e.z, fmaf(w02, f.z, fmaf(w03, h.z, -b0))));
        r0.w = fmaf(w00, a.w, fmaf(w01, e.w, fmaf(w02, f.w, fmaf(w03, h.w, -b0))));
        r1.x = fmaf(w10, a.x, fmaf(w11, e.x, fmaf(w12, f.x, fmaf(w13, h.x, -b1))));
        r1.y = fmaf(w10, a.y, fmaf(w11, e.y, fmaf(w12, f.y, fmaf(w13, h.y, -b1))));
        r1.z = fmaf(w10, a.z, fmaf(w11, e.z, fmaf(w12, f.z, fmaf(w13, h.z, -b1))));
        r1.w = fmaf(w10, a.w, fmaf(w11, e.w, fmaf(w12, f.w, fmaf(w13, h.w, -b1))));
        r2.x = fmaf(w20, a.x, fmaf(w21, e.x, fmaf(w22, f.x, fmaf(w23, h.x, -b2))));
        r2.y = fmaf(w20, a.y, fmaf(w21, e.y, fmaf(w22, f.y, fmaf(w23, h.y, -b2))));
        r2.z = fmaf(w20, a.z, fmaf(w21, e.z, fmaf(w22, f.z, fmaf(w23, h.z, -b2))));
        r2.w = fmaf(w20, a.w, fmaf(w21, e.w, fmaf(w22, f.w, fmaf(w23, h.w, -b2))));
        r3.x = fmaf(w30, a.x, fmaf(w31, e.x, fmaf(w32, f.x, fmaf(w33, h.x, -b3))));
        r3.y = fmaf(w30, a.y, fmaf(w31, e.y, fmaf(w32, f.y, fmaf(w33, h.y, -b3))));
        r3.z = fmaf(w30, a.z, fmaf(w31, e.z, fmaf(w32, f.z, fmaf(w33, h.z, -b3))));
        r3.w = fmaf(w30, a.w, fmaf(w31, e.w, fmaf(w32, f.w, fmaf(w33, h.w, -b3))));

        __stcs(o0 + i, r0);
        __stcs(o1 + i, r1);
        __stcs(o2 + i, r2);
        __stcs(o3 + i, r3);
    }
}

// ---------------------------------------------------------------------------
extern "C" void kernel_launch(void* const* d_in, const int* in_sizes, int n_in,
                              void* d_out, int out_size) {
    const float* x = (const float*)d_in[0];
    float* out = (float*)d_out;
    whiten_pipelined<<<dim3(NB, NG), 256>>>(x, out);
}

// round 12
// speedup vs baseline: 1.3364x; 1.3364x over previous
#include <cuda_runtime.h>

// Group ZCA whitening: x (64, 256, 56, 56) fp32, 64 groups of 4 channels.
// R12: R10 base (best: 108.6us) with two stats-side changes:
//  (1) no __launch_bounds__ on stats -> natural 40-reg/72%-occ codegen (R5's
//      measured optimum for the pure-read stream);
//  (2) Jacobi early-exit loosened to 1e-6f relative -> ~2-3 sweeps on this
//      well-conditioned covariance, shortening the inline-solve tail.
// Apply identical to R10: reversed bid order (L2 residue), __ldcs/__stcs.

#define NB   64      // batches
#define NG   64      // groups
#define NCH  256     // channels
#define SP   3136    // 56*56
#define SP4  784     // SP / 4
#define EPSF 1e-3f

__device__ float g_part[NG * NB * 14];   // [group][batch][4 sums + 10 moments]
__device__ float g_W[NG * 16];
__device__ float g_bias[NG * 4];
__device__ unsigned int g_cnt[NG];       // per-group arrival counters (self-resetting)

// ---------------------------------------------------------------------------
// fp32 4x4 symmetric Jacobi solve for group g (validated R8/R10: rel_err
// ~3.6e-7). Called by the last-arriving stats block of that group.
// ---------------------------------------------------------------------------
__device__ void solve_group(int g) {
    const int t = threadIdx.x;

    float vals[14];
    if (t < NB) {
        #pragma unroll
        for (int k = 0; k < 14; k++)
            vals[k] = g_part[((size_t)g * NB + t) * 14 + k];
    } else {
        #pragma unroll
        for (int k = 0; k < 14; k++) vals[k] = 0.f;
    }

    const int lane = t & 31;
    const int warp = t >> 5;
    #pragma unroll
    for (int k = 0; k < 14; k++) {
        #pragma unroll
        for (int o = 16; o > 0; o >>= 1)
            vals[k] += __shfl_down_sync(0xffffffffu, vals[k], o);
    }
    __shared__ float sv[2][14];
    if (lane == 0 && warp < 2) {
        #pragma unroll
        for (int k = 0; k < 14; k++) sv[warp][k] = vals[k];
    }
    __syncthreads();

    if (t == 0) {
        float S[4], Q[10];
        #pragma unroll
        for (int k = 0; k < 4; k++) S[k] = sv[0][k] + sv[1][k];
        #pragma unroll
        for (int k = 0; k < 10; k++) Q[k] = sv[0][4 + k] + sv[1][4 + k];

        const float n = (float)NB * (float)SP;
        float m[4];
        #pragma unroll
        for (int k = 0; k < 4; k++) m[k] = S[k] / n;

        float A[4][4];
        const int qi[4][4] = {{0,1,2,3},{1,4,5,6},{2,5,7,8},{3,6,8,9}};
        for (int i = 0; i < 4; i++)
            for (int j = 0; j < 4; j++) {
                float c = Q[qi[i][j]] - n * m[i] * m[j];
                A[i][j] = (1.0f - EPSF) * c + (i == j ? EPSF : 0.0f);
            }

        float V[4][4] = {{1,0,0,0},{0,1,0,0},{0,0,1,0},{0,0,0,1}};
        for (int sweep = 0; sweep < 12; sweep++) {
            float off = fabsf(A[0][1]) + fabsf(A[0][2]) + fabsf(A[0][3])
                      + fabsf(A[1][2]) + fabsf(A[1][3]) + fabsf(A[2][3]);
            if (off < 1e-6f * (fabsf(A[0][0]) + fabsf(A[1][1]) + fabsf(A[2][2]) + fabsf(A[3][3]) + 1e-30f))
                break;
            for (int p = 0; p < 3; p++)
                for (int q = p + 1; q < 4; q++) {
                    float apq = A[p][q];
                    if (fabsf(apq) < 1e-30f) continue;
                    float theta = (A[q][q] - A[p][p]) / (2.0f * apq);
                    float tt = (theta >= 0.0f ? 1.0f : -1.0f) / (fabsf(theta) + sqrtf(theta * theta + 1.0f));
                    float c = 1.0f / sqrtf(tt * tt + 1.0f);
                    float s = tt * c;
                    for (int k = 0; k < 4; k++) {
                        float akp = A[k][p], akq = A[k][q];
                        A[k][p] = c * akp - s * akq;
                        A[k][q] = s * akp + c * akq;
                    }
                    for (int k = 0; k < 4; k++) {
                        float apk = A[p][k], aqk = A[q][k];
                        A[p][k] = c * apk - s * aqk;
                        A[q][k] = s * apk + c * aqk;
                    }
                    for (int k = 0; k < 4; k++) {
                        float vkp = V[k][p], vkq = V[k][q];
                        V[k][p] = c * vkp - s * vkq;
                        V[k][q] = s * vkp + c * vkq;
                    }
                }
        }

        float inv[4];
        #pragma unroll
        for (int k = 0; k < 4; k++) inv[k] = 1.0f / sqrtf(A[k][k] + EPSF);

        for (int i = 0; i < 4; i++) {
            float bsum = 0.0f;
            #pragma unroll
            for (int j = 0; j < 4; j++) {
                float w = 0.0f;
                #pragma unroll
                for (int k = 0; k < 4; k++) w += V[i][k] * inv[k] * V[j][k];
                g_W[g * 16 + i * 4 + j] = w;
                bsum += w * m[j];
            }
            g_bias[g * 4 + i] = bsum;
        }
    }
}

// ---------------------------------------------------------------------------
// Pass 1: stats + inline last-block solve. grid (NG, NB), 256 threads.
// No launch_bounds: natural codegen (40 regs, 72% occ -- measured optimum).
// ---------------------------------------------------------------------------
__global__ void stats_kernel(const float* __restrict__ x) {
    const int g = blockIdx.x;
    const int b = blockIdx.y;
    const int tid = threadIdx.x;
    const size_t base = ((size_t)b * NCH + (size_t)g * 4) * SP;
    const float4* __restrict__ c0 = (const float4*)(x + base);
    const float4* __restrict__ c1 = c0 + SP4;
    const float4* __restrict__ c2 = c0 + 2 * SP4;
    const float4* __restrict__ c3 = c0 + 3 * SP4;

    float s0 = 0.f, s1 = 0.f, s2 = 0.f, s3 = 0.f;
    float q00 = 0.f, q01 = 0.f, q02 = 0.f, q03 = 0.f;
    float q11 = 0.f, q12 = 0.f, q13 = 0.f;
    float q22 = 0.f, q23 = 0.f, q33 = 0.f;

    for (int i = tid; i < SP4; i += 256) {
        float4 a = c0[i];
        float4 e = c1[i];
        float4 f = c2[i];
        float4 h = c3[i];
        s0 += a.x + a.y + a.z + a.w;
        s1 += e.x + e.y + e.z + e.w;
        s2 += f.x + f.y + f.z + f.w;
        s3 += h.x + h.y + h.z + h.w;
        q00 += a.x*a.x + a.y*a.y + a.z*a.z + a.w*a.w;
        q01 += a.x*e.x + a.y*e.y + a.z*e.z + a.w*e.w;
        q02 += a.x*f.x + a.y*f.y + a.z*f.z + a.w*f.w;
        q03 += a.x*h.x + a.y*h.y + a.z*h.z + a.w*h.w;
        q11 += e.x*e.x + e.y*e.y + e.z*e.z + e.w*e.w;
        q12 += e.x*f.x + e.y*f.y + e.z*f.z + e.w*f.w;
        q13 += e.x*h.x + e.y*h.y + e.z*h.z + e.w*h.w;
        q22 += f.x*f.x + f.y*f.y + f.z*f.z + f.w*f.w;
        q23 += f.x*h.x + f.y*h.y + f.z*h.z + f.w*h.w;
        q33 += h.x*h.x + h.y*h.y + h.z*h.z + h.w*h.w;
    }

    float vals[14] = {s0, s1, s2, s3, q00, q01, q02, q03, q11, q12, q13, q22, q23, q33};

    const int lane = tid & 31;
    const int warp = tid >> 5;
    #pragma unroll
    for (int k = 0; k < 14; k++) {
        #pragma unroll
        for (int o = 16; o > 0; o >>= 1)
            vals[k] += __shfl_down_sync(0xffffffffu, vals[k], o);
    }

    __shared__ float sm[8][14];
    if (lane == 0) {
        #pragma unroll
        for (int k = 0; k < 14; k++) sm[warp][k] = vals[k];
    }
    __syncthreads();
    if (tid < 14) {
        float t = 0.f;
        #pragma unroll
        for (int w = 0; w < 8; w++) t += sm[w][tid];
        g_part[((size_t)g * NB + b) * 14 + tid] = t;
    }

    // Last-block-done: the 64th block for this group solves it inline.
    __shared__ unsigned int is_last;
    __syncthreads();
    if (tid == 0) {
        __threadfence();                       // publish g_part writes
        unsigned int old = atomicAdd(&g_cnt[g], 1u);
        is_last = (old == NB - 1u) ? 1u : 0u;
        if (is_last) atomicExch(&g_cnt[g], 0u);  // reset for graph replay
    }
    __syncthreads();
    if (is_last) {
        solve_group(g);
    }
}

// ---------------------------------------------------------------------------
// Pass 2: apply. grid (NG, NB), bid order fully REVERSED vs stats so the first
// apply blocks consume the most-recently-read (L2-resident) x addresses.
// ---------------------------------------------------------------------------
__global__ __launch_bounds__(256) void apply_kernel(const float* __restrict__ x,
                                                    float* __restrict__ out) {
    const int g = NG - 1 - blockIdx.x;   // reverse g (fast dim)
    const int b = NB - 1 - blockIdx.y;   // reverse b (slow dim)
    const int tid = threadIdx.x;

    __shared__ float Ws[20];
    if (tid < 16) Ws[tid] = g_W[g * 16 + tid];
    if (tid < 4)  Ws[16 + tid] = g_bias[g * 4 + tid];
    __syncthreads();

    const float w00 = Ws[0],  w01 = Ws[1],  w02 = Ws[2],  w03 = Ws[3];
    const float w10 = Ws[4],  w11 = Ws[5],  w12 = Ws[6],  w13 = Ws[7];
    const float w20 = Ws[8],  w21 = Ws[9],  w22 = Ws[10], w23 = Ws[11];
    const float w30 = Ws[12], w31 = Ws[13], w32 = Ws[14], w33 = Ws[15];
    const float b0 = Ws[16], b1 = Ws[17], b2 = Ws[18], b3 = Ws[19];

    const size_t base = ((size_t)b * NCH + (size_t)g * 4) * SP;
    const float4* __restrict__ c0 = (const float4*)(x + base);
    const float4* __restrict__ c1 = c0 + SP4;
    const float4* __restrict__ c2 = c0 + 2 * SP4;
    const float4* __restrict__ c3 = c0 + 3 * SP4;
    float4* __restrict__ o0 = (float4*)(out + base);
    float4* __restrict__ o1 = o0 + SP4;
    float4* __restrict__ o2 = o0 + 2 * SP4;
    float4* __restrict__ o3 = o0 + 3 * SP4;

    for (int i = tid; i < SP4; i += 256) {
        float4 a = __ldcs(c0 + i);
        float4 e = __ldcs(c1 + i);
        float4 f = __ldcs(c2 + i);
        float4 h = __ldcs(c3 + i);

        float4 r0, r1, r2, r3;
        r0.x = fmaf(w00, a.x, fmaf(w01, e.x, fmaf(w02, f.x, fmaf(w03, h.x, -b0))));
        r0.y = fmaf(w00, a.y, fmaf(w01, e.y, fmaf(w02, f.y, fmaf(w03, h.y, -b0))));
        r0.z = fmaf(w00, a.z, fmaf(w01, e.z, fmaf(w02, f.z, fmaf(w03, h.z, -b0))));
        r0.w = fmaf(w00, a.w, fmaf(w01, e.w, fmaf(w02, f.w, fmaf(w03, h.w, -b0))));
        r1.x = fmaf(w10, a.x, fmaf(w11, e.x, fmaf(w12, f.x, fmaf(w13, h.x, -b1))));
        r1.y = fmaf(w10, a.y, fmaf(w11, e.y, fmaf(w12, f.y, fmaf(w13, h.y, -b1))));
        r1.z = fmaf(w10, a.z, fmaf(w11, e.z, fmaf(w12, f.z, fmaf(w13, h.z, -b1))));
        r1.w = fmaf(w10, a.w, fmaf(w11, e.w, fmaf(w12, f.w, fmaf(w13, h.w, -b1))));
        r2.x = fmaf(w20, a.x, fmaf(w21, e.x, fmaf(w22, f.x, fmaf(w23, h.x, -b2))));
        r2.y = fmaf(w20, a.y, fmaf(w21, e.y, fmaf(w22, f.y, fmaf(w23, h.y, -b2))));
        r2.z = fmaf(w20, a.z, fmaf(w21, e.z, fmaf(w22, f.z, fmaf(w23, h.z, -b2))));
        r2.w = fmaf(w20, a.w, fmaf(w21, e.w, fmaf(w22, f.w, fmaf(w23, h.w, -b2))));
        r3.x = fmaf(w30, a.x, fmaf(w31, e.x, fmaf(w32, f.x, fmaf(w33, h.x, -b3))));
        r3.y = fmaf(w30, a.y, fmaf(w31, e.y, fmaf(w32, f.y, fmaf(w33, h.y, -b3))));
        r3.z = fmaf(w30, a.z, fmaf(w31, e.z, fmaf(w32, f.z, fmaf(w33, h.z, -b3))));
        r3.w = fmaf(w30, a.w, fmaf(w31, e.w, fmaf(w32, f.w, fmaf(w33, h.w, -b3))));

        __stcs(o0 + i, r0);
        __stcs(o1 + i, r1);
        __stcs(o2 + i, r2);
        __stcs(o3 + i, r3);
    }
}

// ---------------------------------------------------------------------------
extern "C" void kernel_launch(void* const* d_in, const int* in_sizes, int n_in,
                              void* d_out, int out_size) {
    const float* x = (const float*)d_in[0];
    float* out = (float*)d_out;

    stats_kernel<<<dim3(NG, NB), 256>>>(x);
    apply_kernel<<<dim3(NG, NB), 256>>>(x, out);
}

// round 13
// speedup vs baseline: 1.3439x; 1.0056x over previous
#include <cuda_runtime.h>

// Group ZCA whitening: x (64, 256, 56, 56) fp32, 64 groups of 4 channels.
// R13: R10 base with stats grid swapped to (NB, NG), b FASTEST: group g's 64
// blocks are consecutive bids g*64..g*64+63, so groups complete EARLY and
// staggered -> the 64 inline solves trickle during streaming instead of
// piling into a dead tail after the last wave. No in-kernel waiting anywhere.
// Apply: same grid, fully reversed mapping (L2 residue), __ldcs/__stcs.

#define NB   64      // batches
#define NG   64      // groups
#define NCH  256     // channels
#define SP   3136    // 56*56
#define SP4  784     // SP / 4
#define EPSF 1e-3f

__device__ float g_part[NG * NB * 14];   // [group][batch][4 sums + 10 moments]
__device__ float g_W[NG * 16];
__device__ float g_bias[NG * 4];
__device__ unsigned int g_cnt[NG];       // per-group arrival counters (self-resetting)

// ---------------------------------------------------------------------------
// fp32 4x4 symmetric Jacobi solve for group g (validated: rel_err ~4.8e-7).
// Run by the last-arriving stats block of the group, overlapped with other
// groups' streaming.
// ---------------------------------------------------------------------------
__device__ void solve_group(int g) {
    const int t = threadIdx.x;

    float vals[14];
    if (t < NB) {
        #pragma unroll
        for (int k = 0; k < 14; k++)
            vals[k] = g_part[((size_t)g * NB + t) * 14 + k];
    } else {
        #pragma unroll
        for (int k = 0; k < 14; k++) vals[k] = 0.f;
    }

    const int lane = t & 31;
    const int warp = t >> 5;
    #pragma unroll
    for (int k = 0; k < 14; k++) {
        #pragma unroll
        for (int o = 16; o > 0; o >>= 1)
            vals[k] += __shfl_down_sync(0xffffffffu, vals[k], o);
    }
    __shared__ float sv[2][14];
    if (lane == 0 && warp < 2) {
        #pragma unroll
        for (int k = 0; k < 14; k++) sv[warp][k] = vals[k];
    }
    __syncthreads();

    if (t == 0) {
        float S[4], Q[10];
        #pragma unroll
        for (int k = 0; k < 4; k++) S[k] = sv[0][k] + sv[1][k];
        #pragma unroll
        for (int k = 0; k < 10; k++) Q[k] = sv[0][4 + k] + sv[1][4 + k];

        const float n = (float)NB * (float)SP;
        float m[4];
        #pragma unroll
        for (int k = 0; k < 4; k++) m[k] = S[k] / n;

        float A[4][4];
        const int qi[4][4] = {{0,1,2,3},{1,4,5,6},{2,5,7,8},{3,6,8,9}};
        for (int i = 0; i < 4; i++)
            for (int j = 0; j < 4; j++) {
                float c = Q[qi[i][j]] - n * m[i] * m[j];
                A[i][j] = (1.0f - EPSF) * c + (i == j ? EPSF : 0.0f);
            }

        float V[4][4] = {{1,0,0,0},{0,1,0,0},{0,0,1,0},{0,0,0,1}};
        for (int sweep = 0; sweep < 12; sweep++) {
            float off = fabsf(A[0][1]) + fabsf(A[0][2]) + fabsf(A[0][3])
                      + fabsf(A[1][2]) + fabsf(A[1][3]) + fabsf(A[2][3]);
            if (off < 1e-6f * (fabsf(A[0][0]) + fabsf(A[1][1]) + fabsf(A[2][2]) + fabsf(A[3][3]) + 1e-30f))
                break;
            for (int p = 0; p < 3; p++)
                for (int q = p + 1; q < 4; q++) {
                    float apq = A[p][q];
                    if (fabsf(apq) < 1e-30f) continue;
                    float theta = (A[q][q] - A[p][p]) / (2.0f * apq);
                    float tt = (theta >= 0.0f ? 1.0f : -1.0f) / (fabsf(theta) + sqrtf(theta * theta + 1.0f));
                    float c = 1.0f / sqrtf(tt * tt + 1.0f);
                    float s = tt * c;
                    for (int k = 0; k < 4; k++) {
                        float akp = A[k][p], akq = A[k][q];
                        A[k][p] = c * akp - s * akq;
                        A[k][q] = s * akp + c * akq;
                    }
                    for (int k = 0; k < 4; k++) {
                        float apk = A[p][k], aqk = A[q][k];
                        A[p][k] = c * apk - s * aqk;
                        A[q][k] = s * apk + c * aqk;
                    }
                    for (int k = 0; k < 4; k++) {
                        float vkp = V[k][p], vkq = V[k][q];
                        V[k][p] = c * vkp - s * vkq;
                        V[k][q] = s * vkp + c * vkq;
                    }
                }
        }

        float inv[4];
        #pragma unroll
        for (int k = 0; k < 4; k++) inv[k] = 1.0f / sqrtf(A[k][k] + EPSF);

        for (int i = 0; i < 4; i++) {
            float bsum = 0.0f;
            #pragma unroll
            for (int j = 0; j < 4; j++) {
                float w = 0.0f;
                #pragma unroll
                for (int k = 0; k < 4; k++) w += V[i][k] * inv[k] * V[j][k];
                g_W[g * 16 + i * 4 + j] = w;
                bsum += w * m[j];
            }
            g_bias[g * 4 + i] = bsum;
        }
    }
}

// ---------------------------------------------------------------------------
// Pass 1: stats + inline last-block solve. grid (NB, NG): b = blockIdx.x
// (FAST) => group g occupies consecutive bids, completes early, solve trickles.
// ---------------------------------------------------------------------------
__global__ __launch_bounds__(256, 6) void stats_kernel(const float* __restrict__ x) {
    const int b = blockIdx.x;
    const int g = blockIdx.y;
    const int tid = threadIdx.x;
    const size_t base = ((size_t)b * NCH + (size_t)g * 4) * SP;
    const float4* __restrict__ c0 = (const float4*)(x + base);
    const float4* __restrict__ c1 = c0 + SP4;
    const float4* __restrict__ c2 = c0 + 2 * SP4;
    const float4* __restrict__ c3 = c0 + 3 * SP4;

    float s0 = 0.f, s1 = 0.f, s2 = 0.f, s3 = 0.f;
    float q00 = 0.f, q01 = 0.f, q02 = 0.f, q03 = 0.f;
    float q11 = 0.f, q12 = 0.f, q13 = 0.f;
    float q22 = 0.f, q23 = 0.f, q33 = 0.f;

    for (int i = tid; i < SP4; i += 256) {
        float4 a = c0[i];
        float4 e = c1[i];
        float4 f = c2[i];
        float4 h = c3[i];
        s0 += a.x + a.y + a.z + a.w;
        s1 += e.x + e.y + e.z + e.w;
        s2 += f.x + f.y + f.z + f.w;
        s3 += h.x + h.y + h.z + h.w;
        q00 += a.x*a.x + a.y*a.y + a.z*a.z + a.w*a.w;
        q01 += a.x*e.x + a.y*e.y + a.z*e.z + a.w*e.w;
        q02 += a.x*f.x + a.y*f.y + a.z*f.z + a.w*f.w;
        q03 += a.x*h.x + a.y*h.y + a.z*h.z + a.w*h.w;
        q11 += e.x*e.x + e.y*e.y + e.z*e.z + e.w*e.w;
        q12 += e.x*f.x + e.y*f.y + e.z*f.z + e.w*f.w;
        q13 += e.x*h.x + e.y*h.y + e.z*h.z + e.w*h.w;
        q22 += f.x*f.x + f.y*f.y + f.z*f.z + f.w*f.w;
        q23 += f.x*h.x + f.y*h.y + f.z*h.z + f.w*h.w;
        q33 += h.x*h.x + h.y*h.y + h.z*h.z + h.w*h.w;
    }

    float vals[14] = {s0, s1, s2, s3, q00, q01, q02, q03, q11, q12, q13, q22, q23, q33};

    const int lane = tid & 31;
    const int warp = tid >> 5;
    #pragma unroll
    for (int k = 0; k < 14; k++) {
        #pragma unroll
        for (int o = 16; o > 0; o >>= 1)
            vals[k] += __shfl_down_sync(0xffffffffu, vals[k], o);
    }

    __shared__ float sm[8][14];
    if (lane == 0) {
        #pragma unroll
        for (int k = 0; k < 14; k++) sm[warp][k] = vals[k];
    }
    __syncthreads();
    if (tid < 14) {
        float t = 0.f;
        #pragma unroll
        for (int w = 0; w < 8; w++) t += sm[w][tid];
        g_part[((size_t)g * NB + b) * 14 + tid] = t;
    }

    // Last-block-done: the 64th arrival for this group solves it inline.
    __shared__ unsigned int is_last;
    __syncthreads();
    if (tid == 0) {
        __threadfence();                       // publish g_part writes
        unsigned int old = atomicAdd(&g_cnt[g], 1u);
        is_last = (old == NB - 1u) ? 1u : 0u;
        if (is_last) atomicExch(&g_cnt[g], 0u);  // reset for graph replay
    }
    __syncthreads();
    if (is_last) {
        solve_group(g);
    }
}

// ---------------------------------------------------------------------------
// Pass 2: apply. grid (NB, NG), bid order fully REVERSED vs stats so the first
// apply blocks consume the most-recently-read (L2-resident) x addresses.
// ---------------------------------------------------------------------------
__global__ __launch_bounds__(256) void apply_kernel(const float* __restrict__ x,
                                                    float* __restrict__ out) {
    const int b = NB - 1 - blockIdx.x;   // reverse b (fast dim)
    const int g = NG - 1 - blockIdx.y;   // reverse g (slow dim)
    const int tid = threadIdx.x;

    __shared__ float Ws[20];
    if (tid < 16) Ws[tid] = g_W[g * 16 + tid];
    if (tid < 4)  Ws[16 + tid] = g_bias[g * 4 + tid];
    __syncthreads();

    const float w00 = Ws[0],  w01 = Ws[1],  w02 = Ws[2],  w03 = Ws[3];
    const float w10 = Ws[4],  w11 = Ws[5],  w12 = Ws[6],  w13 = Ws[7];
    const float w20 = Ws[8],  w21 = Ws[9],  w22 = Ws[10], w23 = Ws[11];
    const float w30 = Ws[12], w31 = Ws[13], w32 = Ws[14], w33 = Ws[15];
    const float b0 = Ws[16], b1 = Ws[17], b2 = Ws[18], b3 = Ws[19];

    const size_t base = ((size_t)b * NCH + (size_t)g * 4) * SP;
    const float4* __restrict__ c0 = (const float4*)(x + base);
    const float4* __restrict__ c1 = c0 + SP4;
    const float4* __restrict__ c2 = c0 + 2 * SP4;
    const float4* __restrict__ c3 = c0 + 3 * SP4;
    float4* __restrict__ o0 = (float4*)(out + base);
    float4* __restrict__ o1 = o0 + SP4;
    float4* __restrict__ o2 = o0 + 2 * SP4;
    float4* __restrict__ o3 = o0 + 3 * SP4;

    for (int i = tid; i < SP4; i += 256) {
        float4 a = __ldcs(c0 + i);
        float4 e = __ldcs(c1 + i);
        float4 f = __ldcs(c2 + i);
        float4 h = __ldcs(c3 + i);

        float4 r0, r1, r2, r3;
        r0.x = fmaf(w00, a.x, fmaf(w01, e.x, fmaf(w02, f.x, fmaf(w03, h.x, -b0))));
        r0.y = fmaf(w00, a.y, fmaf(w01, e.y, fmaf(w02, f.y, fmaf(w03, h.y, -b0))));
        r0.z = fmaf(w00, a.z, fmaf(w01, e.z, fmaf(w02, f.z, fmaf(w03, h.z, -b0))));
        r0.w = fmaf(w00, a.w, fmaf(w01, e.w, fmaf(w02, f.w, fmaf(w03, h.w, -b0))));
        r1.x = fmaf(w10, a.x, fmaf(w11, e.x, fmaf(w12, f.x, fmaf(w13, h.x, -b1))));
        r1.y = fmaf(w10, a.y, fmaf(w11, e.y, fmaf(w12, f.y, fmaf(w13, h.y, -b1))));
        r1.z = fmaf(w10, a.z, fmaf(w11, e.z, fmaf(w12, f.z, fmaf(w13, h.z, -b1))));
        r1.w = fmaf(w10, a.w, fmaf(w11, e.w, fmaf(w12, f.w, fmaf(w13, h.w, -b1))));
        r2.x = fmaf(w20, a.x, fmaf(w21, e.x, fmaf(w22, f.x, fmaf(w23, h.x, -b2))));
        r2.y = fmaf(w20, a.y, fmaf(w21, e.y, fmaf(w22, f.y, fmaf(w23, h.y, -b2))));
        r2.z = fmaf(w20, a.z, fmaf(w21, e.z, fmaf(w22, f.z, fmaf(w23, h.z, -b2))));
        r2.w = fmaf(w20, a.w, fmaf(w21, e.w, fmaf(w22, f.w, fmaf(w23, h.w, -b2))));
        r3.x = fmaf(w30, a.x, fmaf(w31, e.x, fmaf(w32, f.x, fmaf(w33, h.x, -b3))));
        r3.y = fmaf(w30, a.y, fmaf(w31, e.y, fmaf(w32, f.y, fmaf(w33, h.y, -b3))));
        r3.z = fmaf(w30, a.z, fmaf(w31, e.z, fmaf(w32, f.z, fmaf(w33, h.z, -b3))));
        r3.w = fmaf(w30, a.w, fmaf(w31, e.w, fmaf(w32, f.w, fmaf(w33, h.w, -b3))));

        __stcs(o0 + i, r0);
        __stcs(o1 + i, r1);
        __stcs(o2 + i, r2);
        __stcs(o3 + i, r3);
    }
}

// ---------------------------------------------------------------------------
extern "C" void kernel_launch(void* const* d_in, const int* in_sizes, int n_in,
                              void* d_out, int out_size) {
    const float* x = (const float*)d_in[0];
    float* out = (float*)d_out;

    stats_kernel<<<dim3(NB, NG), 256>>>(x);
    apply_kernel<<<dim3(NB, NG), 256>>>(x, out);
}